// round 7
// baseline (speedup 1.0000x reference)
#include <cuda_runtime.h>
#include <cstdint>

// ---------------------------------------------------------------------------
// Sinkhorn-Knopp, 65536 independent 32x32 fp32 matrices, 10 iterations.
//
// M after k normalizations == diag(u) * M0 * diag(v)  -> iterate only u, v:
//   d_i = sum_j M0[i][j] v_j ;  u_i <- u_i / (u_i d_i + eps)
//   c_j = sum_i M0[i][j] u_i ;  v_j <- v_j / (v_j c_j + eps)
//
// One warp per matrix, 8x4 lane grid: a = lane>>2 (rows), b = lane&3 (cols),
// g = a>>1. xor-slot REGISTER layout (iteration is pure shfl_xor, SEL-free):
//   row slot r      <-> actual row       4a + (b^r)
//   col pair slot k <-> actual col pair  g^k  of group b (cols 8b+2(g^k),+1)
//
// Global I/O is perfectly flat (512B/warp-inst). The flat <-> xor-slot
// mapping goes through a per-warp padded smem tile (stride 36 floats); all
// smem ops are 128-bit and bank-conflict-free. v is kept as an f32x2 pair
// replicated across duo lanes (lanes differing in bit2) so the col-reduce
// tail and V[0] formation need no routing selects.
// ---------------------------------------------------------------------------

#define FMA2(d, a, b, c) \
    asm("fma.rn.f32x2 %0, %1, %2, %3;" : "=l"(d) : "l"(a), "l"(b), "l"(c))
#define MUL2(d, a, b) \
    asm("mul.rn.f32x2 %0, %1, %2;" : "=l"(d) : "l"(a), "l"(b))
#define ADD2(d, a, b) \
    asm("add.rn.f32x2 %0, %1, %2;" : "=l"(d) : "l"(a), "l"(b))
#define PACK2(d, lo, hi) \
    asm("mov.b64 %0, {%1, %2};" : "=l"(d) : "f"(lo), "f"(hi))
#define UNPACK2(lo, hi, s) \
    asm("mov.b64 {%0, %1}, %2;" : "=f"(lo), "=f"(hi) : "l"(s))
#define RCPA(d, s) \
    asm("rcp.approx.f32 %0, %1;" : "=f"(d) : "f"(s))
#define EX2A(d, s) \
    asm("ex2.approx.f32 %0, %1;" : "=f"(d) : "f"(s))

using ull = unsigned long long;

static constexpr float    EPS   = 1e-8f;
static constexpr float    SCALE = 14.4269504088896340736f;  // 10 * log2(e)
static constexpr int      WPB   = 4;                        // warps per block
static constexpr int      SROW  = 36;                       // smem row stride
static constexpr unsigned FULL  = 0xFFFFFFFFu;

__device__ __forceinline__ ull shfl_xor64(ull x, int mask) {
    return __shfl_xor_sync(FULL, x, mask);   // 2 SASS SHFLs
}

__global__ __launch_bounds__(WPB * 32, 8)
void sinkhorn_kernel(const float* __restrict__ H,
                     float* __restrict__ Out,
                     int nmat) {
    __shared__ __align__(16) float S[WPB][32 * SROW];

    const int lane = threadIdx.x & 31;
    const int wid  = threadIdx.x >> 5;
    const int a    = lane >> 2;      // 0..7 (rows 4a..4a+3)
    const int b    = lane & 3;       // 0..3 (cols 8b..8b+7)
    const int g    = a >> 1;         // 0..3 (own col-pair index in group)
    const int g0   = g & 1;          // pair-swap bit
    const int g1   = g >> 1;         // chunk-select bit

    const int m = blockIdx.x * WPB + wid;
    if (m >= nmat) return;           // warp-uniform

    float* s = S[wid];
    const float4* src = reinterpret_cast<const float4*>(H)  + (size_t)m * 256;
    float4*       dst = reinterpret_cast<float4*>(Out)      + (size_t)m * 256;

    ull SC2;  PACK2(SC2, SCALE, SCALE);
    ull ONE2; PACK2(ONE2, 1.0f, 1.0f);
    ull EPS2; PACK2(EPS2, EPS, EPS);

    // ---- Flat load (4 lines/inst), scale+exp+clamp, flat STS.128 ----
#pragma unroll
    for (int k = 0; k < 8; k++) {
        const int f = k * 32 + lane;            // float4 index in matrix
        float4 q = src[f];
        ull p0, p1;
        PACK2(p0, q.x, q.y);
        PACK2(p1, q.z, q.w);
        MUL2(p0, p0, SC2);
        MUL2(p1, p1, SC2);
        float x0, y0, x1, y1;
        UNPACK2(x0, y0, p0); UNPACK2(x1, y1, p1);
        EX2A(x0, x0); EX2A(y0, y0); EX2A(x1, x1); EX2A(y1, y1);
        q.x = fmaxf(x0, EPS); q.y = fmaxf(y0, EPS);
        q.z = fmaxf(x1, EPS); q.w = fmaxf(y1, EPS);
        const int row = f >> 3;                 // 8 float4 per row
        const int ch  = f & 7;
        *reinterpret_cast<float4*>(s + row * SROW + ch * 4) = q;
    }
    __syncwarp();

    // ---- Gather xor-slot registers via conflict-free LDS.128 ----
    // chunk Q = 2b + (g1^T) holds col pairs 2Q (lo) and 2Q+1 (hi);
    // slot 2T is the one with pair-bit0 == g0.
    ull M[4][4];
#pragma unroll
    for (int r = 0; r < 4; r++) {
        const int R = 4 * a + (b ^ r);
#pragma unroll
        for (int T = 0; T < 2; T++) {
            const int Q = 2 * b + (g1 ^ T);
            const ulonglong2 q =
                *reinterpret_cast<const ulonglong2*>(s + R * SROW + 4 * Q);
            M[r][2 * T]     = g0 ? q.y : q.x;
            M[r][2 * T + 1] = g0 ? q.x : q.y;
        }
    }

    // State: u = u[4a+b] (scalar); vp = (v[8b+2g], v[8b+2g+1]) pair,
    // replicated across the duo (lanes a, a^1).
    float u = 1.0f;
    ull vp = ONE2;
    ull V[4];                       // V[k] = v-pair for pair g^k of group b
    V[0] = ONE2; V[1] = ONE2; V[2] = ONE2; V[3] = ONE2;
    ull U2[4];                      // U2[r] = (u[4a+(b^r)], same)

#pragma unroll 1
    for (int it = 0; it < 10; it++) {
        // ===== Row step =====
        float D0, D1, D2, D3;
        {
            ull acc;
            MUL2(acc, M[0][0], V[0]); FMA2(acc, M[0][1], V[1], acc);
            FMA2(acc, M[0][2], V[2], acc); FMA2(acc, M[0][3], V[3], acc);
            float x, y; UNPACK2(x, y, acc); D0 = x + y;
            MUL2(acc, M[1][0], V[0]); FMA2(acc, M[1][1], V[1], acc);
            FMA2(acc, M[1][2], V[2], acc); FMA2(acc, M[1][3], V[3], acc);
            UNPACK2(x, y, acc); D1 = x + y;
            MUL2(acc, M[2][0], V[0]); FMA2(acc, M[2][1], V[1], acc);
            FMA2(acc, M[2][2], V[2], acc); FMA2(acc, M[2][3], V[3], acc);
            UNPACK2(x, y, acc); D2 = x + y;
            MUL2(acc, M[3][0], V[0]); FMA2(acc, M[3][1], V[1], acc);
            FMA2(acc, M[3][2], V[2], acc); FMA2(acc, M[3][3], V[3], acc);
            UNPACK2(x, y, acc); D3 = x + y;
        }
        // xor-slot reduce over b-quad (slot r on lane b holds row 4a+(b^r))
        D0 += __shfl_xor_sync(FULL, D2, 2);
        D1 += __shfl_xor_sync(FULL, D3, 2);
        D0 += __shfl_xor_sync(FULL, D1, 1);      // full d[4a+b]
        { float t = fmaf(u, D0, EPS); float r0; RCPA(r0, t); u *= r0; }
        // u allgather into row slots
        {
            float u1 = __shfl_xor_sync(FULL, u, 1);
            float u2 = __shfl_xor_sync(FULL, u, 2);
            float u3 = __shfl_xor_sync(FULL, u, 3);
            PACK2(U2[0], u,  u ); PACK2(U2[1], u1, u1);
            PACK2(U2[2], u2, u2); PACK2(U2[3], u3, u3);
        }

        // ===== Col step =====
        ull C0, C1, C2, C3;
        MUL2(C0, M[0][0], U2[0]); FMA2(C0, M[1][0], U2[1], C0);
        FMA2(C0, M[2][0], U2[2], C0); FMA2(C0, M[3][0], U2[3], C0);
        MUL2(C1, M[0][1], U2[0]); FMA2(C1, M[1][1], U2[1], C1);
        FMA2(C1, M[2][1], U2[2], C1); FMA2(C1, M[3][1], U2[3], C1);
        MUL2(C2, M[0][2], U2[0]); FMA2(C2, M[1][2], U2[1], C2);
        FMA2(C2, M[2][2], U2[2], C2); FMA2(C2, M[3][2], U2[3], C2);
        MUL2(C3, M[0][3], U2[0]); FMA2(C3, M[1][3], U2[1], C3);
        FMA2(C3, M[2][3], U2[2], C3); FMA2(C3, M[3][3], U2[3], C3);
        // xor-slot reduce over the 8 a-lanes (all pair payloads)
        {
            ull t;
            t = shfl_xor64(C2, 16); ADD2(C0, C0, t);
            t = shfl_xor64(C3, 16); ADD2(C1, C1, t);
            t = shfl_xor64(C1, 8);  ADD2(C0, C0, t);
            t = shfl_xor64(C0, 4);  ADD2(C0, C0, t);   // full pair c on duo
        }
        // v-pair update, replicated across duo (no routing selects)
        {
            ull t; FMA2(t, vp, C0, EPS2);
            float tl, th; UNPACK2(tl, th, t);
            float rl, rh; RCPA(rl, tl); RCPA(rh, th);
            ull rp; PACK2(rp, rl, rh);
            MUL2(vp, vp, rp);
        }
        // v allgather into col-pair slots
        V[0] = vp;
        V[1] = shfl_xor64(vp, 8);
        V[2] = shfl_xor64(vp, 16);
        V[3] = shfl_xor64(vp, 24);
    }

    // ---- Epilogue: out[i][j] = u_i * M0[i][j] * v_j ----
    // STS.128 per chunk (conflict-free), then flat LDS.128 + flat STG.128.
#pragma unroll
    for (int r = 0; r < 4; r++) {
        const int R = 4 * a + (b ^ r);
#pragma unroll
        for (int T = 0; T < 2; T++) {
            const int Q = 2 * b + (g1 ^ T);
            ull o0, o1;
            MUL2(o0, M[r][2 * T],     V[2 * T]);
            MUL2(o0, o0, U2[r]);
            MUL2(o1, M[r][2 * T + 1], V[2 * T + 1]);
            MUL2(o1, o1, U2[r]);
            ulonglong2 q;
            q.x = g0 ? o1 : o0;      // undo slot pair-swap
            q.y = g0 ? o0 : o1;
            *reinterpret_cast<ulonglong2*>(s + R * SROW + 4 * Q) = q;
        }
    }
    __syncwarp();
#pragma unroll
    for (int k = 0; k < 8; k++) {
        const int f   = k * 32 + lane;
        const int row = f >> 3;
        const int ch  = f & 7;
        dst[f] = *reinterpret_cast<const float4*>(s + row * SROW + ch * 4);
    }
}

extern "C" void kernel_launch(void* const* d_in, const int* in_sizes, int n_in,
                              void* d_out, int out_size) {
    const float* H   = (const float*)d_in[0];
    float*       out = (float*)d_out;
    const int nmat   = in_sizes[0] / 1024;          // 32*32 per matrix
    const int blocks = (nmat + WPB - 1) / WPB;
    sinkhorn_kernel<<<blocks, WPB * 32>>>(H, out, nmat);
}